// round 5
// baseline (speedup 1.0000x reference)
#include <cuda_runtime.h>
#include <cuda_bf16.h>
#include <cstdint>
#include <math.h>

// Problem constants
#define Bq   16
#define Tq   1024
#define Dq   512
#define Vq   5000
#define Lq   128
#define VP   5120            // V padded to multiple of 128
#define NT   40              // VP / 128 column tiles
#define BT   (Bq*Tq)         // 16384 rows
#define NEGF (-1e30f)

// ---------------- scratch (static device globals; no allocation) ----------------
__device__ __align__(16) __nv_bfloat16 g_hsb[BT*Dq];      // hs in bf16
__device__ __align__(16) __nv_bfloat16 g_wbf[Dq*VP];      // W in bf16, padded cols zero
__device__ float g_gbuf[BT*130];                          // logits at first-occurrence symbols
__device__ float g_lp[BT*130];                            // log-probs at symbol j (0=blank,1..128=labels)
__device__ float g_partial[BT*NT];                        // per-(row, ntile) exp-sums
__device__ float g_lse[BT];                               // log sum exp per row
__device__ int   g_inv[Bq*Vq];                            // vocab -> first symbol index j (or -1)
__device__ int   g_rep[Bq*129];                           // j -> first occurrence j'
__device__ float g_loss[Bq];

// ---------------- conversion kernels ----------------
__global__ void k_cvt_hs(const float* __restrict__ hs) {
    int i = blockIdx.x * 256 + threadIdx.x;
    if (i < BT*Dq) g_hsb[i] = __float2bfloat16(hs[i]);
}

__global__ void k_cvt_w(const float* __restrict__ W) {
    int i = blockIdx.x * 256 + threadIdx.x;
    if (i < Dq*VP) {
        int d = i / VP, v = i - d*VP;
        g_wbf[i] = (v < Vq) ? __float2bfloat16(W[d*Vq + v]) : __float2bfloat16(0.0f);
    }
}

// ---------------- per-batch symbol maps ----------------
__global__ void k_prep(const int* __restrict__ ys_pad) {
    int b = blockIdx.x, tid = threadIdx.x;
    __shared__ int sym[129];
    if (tid == 0) sym[0] = 0;                              // blank
    if (tid >= 1 && tid <= 128) sym[tid] = ys_pad[b*Lq + tid - 1];
    for (int i = tid; i < Vq; i += 256) g_inv[b*Vq + i] = -1;
    __syncthreads();
    if (tid == 0) {
        for (int j = 0; j <= 128; j++) {
            int v = sym[j];
            if (g_inv[b*Vq + v] < 0) g_inv[b*Vq + v] = j;  // first occurrence
        }
    }
    __syncthreads();
    if (tid <= 128) g_rep[b*129 + tid] = g_inv[b*Vq + sym[tid]];
}

// ---------------- fused bf16 GEMM + exp-sum + symbol gather ----------------
__device__ __forceinline__ void mma_bf16(
    float& d0, float& d1, float& d2, float& d3,
    unsigned a0, unsigned a1, unsigned a2, unsigned a3,
    unsigned b0, unsigned b1)
{
    asm volatile(
        "mma.sync.aligned.m16n8k16.row.col.f32.bf16.bf16.f32 "
        "{%0,%1,%2,%3}, {%4,%5,%6,%7}, {%8,%9}, {%0,%1,%2,%3};\n"
        : "+f"(d0), "+f"(d1), "+f"(d2), "+f"(d3)
        : "r"(a0), "r"(a1), "r"(a2), "r"(a3), "r"(b0), "r"(b1));
}

__global__ __launch_bounds__(256) void k_gemm(const float* __restrict__ bias) {
    const int tid  = threadIdx.x;
    const int lane = tid & 31, wid = tid >> 5;
    const int g  = lane >> 2, tg = lane & 3;
    const int wm = wid & 3,  wn = wid >> 2;         // 4x2 warp grid, warp tile 32x64
    const int n0 = blockIdx.x * 128;
    const int rowg0 = blockIdx.y * 128;             // rows within one batch (128 | 1024)
    const int b = rowg0 >> 10;

    __shared__ __align__(16) __nv_bfloat16 As[128][40];  // [m][k], KPAD=40
    __shared__ __align__(16) __nv_bfloat16 Bs[128][40];  // [n][k]
    __shared__ int   invs[128];
    __shared__ float biass[128];
    __shared__ float rowsum[128][2];

    if (tid < 128) {
        int v = n0 + tid;
        invs[tid]  = (v < Vq) ? g_inv[b*Vq + v] : -1;
        biass[tid] = (v < Vq) ? bias[v] : 0.0f;
    }

    float acc[2][8][4];
    #pragma unroll
    for (int im = 0; im < 2; im++)
        #pragma unroll
        for (int in_ = 0; in_ < 8; in_++)
            #pragma unroll
            for (int c = 0; c < 4; c++) acc[im][in_][c] = 0.0f;

    for (int kt = 0; kt < 16; kt++) {
        int k0 = kt * 32;
        // A tile: 128 rows x 32 k, vectorized 16B
        for (int i = tid; i < 512; i += 256) {
            int r = i >> 2, kp = (i & 3) << 3;
            *reinterpret_cast<uint4*>(&As[r][kp]) =
                *reinterpret_cast<const uint4*>(&g_hsb[(size_t)(rowg0 + r)*Dq + k0 + kp]);
        }
        // B tile: Bs[n][k] = W[k0+k][n0+n]  (coalesced global, transposed smem store)
        for (int i = tid; i < 2048; i += 256) {
            int k = i >> 6, n2 = (i & 63) << 1;
            __nv_bfloat162 w2 = *reinterpret_cast<const __nv_bfloat162*>(
                &g_wbf[(size_t)(k0 + k)*VP + n0 + n2]);
            Bs[n2][k]     = w2.x;
            Bs[n2 + 1][k] = w2.y;
        }
        __syncthreads();

        #pragma unroll
        for (int ks = 0; ks < 2; ks++) {
            int kk = ks << 4;
            unsigned af[2][4];
            #pragma unroll
            for (int im = 0; im < 2; im++) {
                int mb = wm*32 + im*16;
                af[im][0] = *reinterpret_cast<const unsigned*>(&As[mb + g    ][kk + tg*2    ]);
                af[im][1] = *reinterpret_cast<const unsigned*>(&As[mb + g + 8][kk + tg*2    ]);
                af[im][2] = *reinterpret_cast<const unsigned*>(&As[mb + g    ][kk + tg*2 + 8]);
                af[im][3] = *reinterpret_cast<const unsigned*>(&As[mb + g + 8][kk + tg*2 + 8]);
            }
            #pragma unroll
            for (int in_ = 0; in_ < 8; in_++) {
                int nb = wn*64 + in_*8 + g;
                unsigned b0 = *reinterpret_cast<const unsigned*>(&Bs[nb][kk + tg*2    ]);
                unsigned b1 = *reinterpret_cast<const unsigned*>(&Bs[nb][kk + tg*2 + 8]);
                mma_bf16(acc[0][in_][0], acc[0][in_][1], acc[0][in_][2], acc[0][in_][3],
                         af[0][0], af[0][1], af[0][2], af[0][3], b0, b1);
                mma_bf16(acc[1][in_][0], acc[1][in_][1], acc[1][in_][2], acc[1][in_][3],
                         af[1][0], af[1][1], af[1][2], af[1][3], b0, b1);
            }
        }
        __syncthreads();
    }

    // Epilogue: bias add, exp-sum per row, sparse symbol scatter (no max-shift needed:
    // |logit| < ~3, exp is safe in fp32).
    #pragma unroll
    for (int im = 0; im < 2; im++) {
        #pragma unroll
        for (int rh = 0; rh < 2; rh++) {
            int m = wm*32 + im*16 + g + rh*8;
            float s = 0.0f;
            #pragma unroll
            for (int in_ = 0; in_ < 8; in_++) {
                #pragma unroll
                for (int cc = 0; cc < 2; cc++) {
                    int n = wn*64 + in_*8 + tg*2 + cc;
                    float x = acc[im][in_][rh*2 + cc] + biass[n];
                    if (n0 + n < Vq) {
                        s += __expf(x);
                        int j = invs[n];
                        if (j >= 0) g_gbuf[(size_t)(rowg0 + m)*130 + j] = x;
                    }
                }
            }
            s += __shfl_xor_sync(0xffffffffu, s, 1);
            s += __shfl_xor_sync(0xffffffffu, s, 2);
            if (tg == 0) rowsum[m][wn] = s;
        }
    }
    __syncthreads();
    if (tid < 128)
        g_partial[(size_t)(rowg0 + tid)*NT + blockIdx.x] = rowsum[tid][0] + rowsum[tid][1];
}

// ---------------- reduce partial exp-sums -> lse ----------------
__global__ void k_lse() {
    int r = blockIdx.x * 256 + threadIdx.x;
    if (r < BT) {
        float s = 0.0f;
        #pragma unroll
        for (int i = 0; i < NT; i++) s += g_partial[(size_t)r*NT + i];
        g_lse[r] = __logf(s);
    }
}

// ---------------- replicate duplicate symbols + subtract lse ----------------
__global__ void k_dup() {
    int idx = blockIdx.x * 256 + threadIdx.x;
    if (idx < BT*129) {
        int r = idx / 129, j = idx - r*129;
        int b = r >> 10;
        g_lp[(size_t)r*130 + j] = g_gbuf[(size_t)r*130 + g_rep[b*129 + j]] - g_lse[r];
    }
}

// ---------------- CTC forward (one CTA per batch, one thread per state) ----------------
__global__ __launch_bounds__(288) void k_ctc(const int* __restrict__ ys_pad,
                                             const int* __restrict__ hlens,
                                             const int* __restrict__ ys_lens) {
    const int b = blockIdx.x, s = threadIdx.x;   // 288 threads, states 0..256 active
    __shared__ float bufA[259], bufB[259];       // alpha at offset +2 (pads [0..1] = NEG)
    __shared__ int ysS[128];

    const int hl = hlens[b];
    const int yl = ys_lens[b];
    const float* lpb = g_lp + (size_t)b * Tq * 130;

    if (s < 128) ysS[s] = ys_pad[b*Lq + s];
    if (s < 259) { bufA[s] = NEGF; bufB[s] = NEGF; }
    __syncthreads();

    const bool active = (s < 257);
    int jj = 0;
    bool allow = false;
    if (active && (s & 1)) {
        int k = s >> 1;                           // s = 2k+1 -> label k, lp index k+1
        jj = k + 1;
        allow = (k == 0) || (ysS[k] != ysS[k - 1]);
    }

    if (s == 0) bufA[2] = lpb[0];                 // alpha0[0] = lp_ext[0,0] (blank)
    if (s == 1) bufA[3] = lpb[1];                 // alpha0[1] = lp_ext[0,1]
    __syncthreads();

    float* cur = bufA;
    float* nxt = bufB;

    // depth-2 register prefetch of this state's lp stream
    float p0 = 0.0f, p1 = 0.0f;
    if (active) {
        p0 = __ldg(&lpb[(size_t)1 * 130 + jj]);
        p1 = __ldg(&lpb[(size_t)2 * 130 + jj]);
    }

    for (int t = 1; t < hl; t++) {
        float lpv = p0;
        p0 = p1;
        int tn = t + 2; if (tn > Tq - 1) tn = Tq - 1;
        if (active) p1 = __ldg(&lpb[(size_t)tn * 130 + jj]);

        if (active) {
            float a1 = cur[2 + s];
            float a2 = cur[1 + s];
            float a3 = allow ? cur[s] : NEGF;
            float m = fmaxf(fmaxf(a1, a2), a3);
            m = fmaxf(m, NEGF);
            float r = __expf(a1 - m) + __expf(a2 - m) + __expf(a3 - m);
            nxt[2 + s] = m + __logf(r) + lpv;
        }
        __syncthreads();
        float* tmp = cur; cur = nxt; nxt = tmp;
    }

    if (s == 0) {
        int i1 = 2 * yl;
        int i2 = i1 - 1; if (i2 < 0) i2 = 0;
        float a = cur[2 + i1], c = cur[2 + i2];
        float m = fmaxf(a, c);
        float ll = m + __logf(__expf(a - m) + __expf(c - m));
        float L = -ll;
        if (!isfinite(L) || L >= 1e29f) L = 0.0f;  // zero_infinity
        g_loss[b] = L;
    }
}

// ---------------- finalize: sum(loss) / sum(ys_lens) ----------------
__global__ void k_finalize(const int* __restrict__ ys_lens, float* __restrict__ out) {
    int t = threadIdx.x;
    float s  = (t < Bq) ? g_loss[t] : 0.0f;
    float yn = (t < Bq) ? (float)ys_lens[t] : 0.0f;
    #pragma unroll
    for (int o = 16; o > 0; o >>= 1) {
        s  += __shfl_xor_sync(0xffffffffu, s,  o);
        yn += __shfl_xor_sync(0xffffffffu, yn, o);
    }
    if (t == 0) out[0] = s / yn;
}

// ---------------- launch ----------------
extern "C" void kernel_launch(void* const* d_in, const int* in_sizes, int n_in,
                              void* d_out, int out_size) {
    (void)in_sizes; (void)n_in; (void)out_size;
    const float* hs      = (const float*)d_in[0];
    const int*   hlens   = (const int*)  d_in[1];
    const int*   ys_pad  = (const int*)  d_in[2];
    const int*   ys_lens = (const int*)  d_in[3];
    const float* W       = (const float*)d_in[4];
    const float* bias    = (const float*)d_in[5];
    float*       out     = (float*)d_out;

    k_cvt_hs<<<(BT*Dq + 255)/256, 256>>>(hs);
    k_cvt_w <<<(Dq*VP + 255)/256, 256>>>(W);
    k_prep  <<<Bq, 256>>>(ys_pad);
    dim3 gg(NT, BT/128);
    k_gemm  <<<gg, 256>>>(bias);
    k_lse   <<<(BT + 255)/256, 256>>>();
    k_dup   <<<(BT*129 + 255)/256, 256>>>();
    k_ctc   <<<Bq, 288>>>(ys_pad, hlens, ys_lens);
    k_finalize<<<1, 32>>>(ys_lens, out);
}

// round 6
// speedup vs baseline: 1.4522x; 1.4522x over previous
#include <cuda_runtime.h>
#include <cuda_bf16.h>
#include <cstdint>
#include <math.h>

// Problem constants
#define Bq   16
#define Tq   1024
#define Dq   512
#define Vq   5000
#define Lq   128
#define VP   5120            // V padded to multiple of 128
#define NT   40              // VP / 128 column tiles
#define BT   (Bq*Tq)         // 16384 rows
#define NEGF (-1e30f)

// ---------------- scratch (static device globals; no allocation) ----------------
__device__ __align__(16) __nv_bfloat16 g_hsb[BT*Dq];      // hs in bf16
__device__ __align__(16) __nv_bfloat16 g_wt[VP*Dq];       // W transposed: [v][d], bf16, pad rows zero
__device__ float g_gbuf[BT*130];                          // logits at first-occurrence symbols
__device__ float g_lp[BT*130];                            // log-probs at symbol j (0=blank,1..128=labels)
__device__ float g_partial[BT*NT];                        // per-(row, ntile) exp-sums
__device__ int   g_inv[Bq*Vq];                            // vocab -> first symbol index j (or -1)
__device__ int   g_rep[Bq*129];                           // j -> first occurrence j'
__device__ float g_loss[Bq];

// ---------------- helpers ----------------
__device__ __forceinline__ void cp16(void* smem, const void* gmem) {
    uint32_t s = (uint32_t)__cvta_generic_to_shared(smem);
    asm volatile("cp.async.cg.shared.global [%0], [%1], 16;\n" :: "r"(s), "l"(gmem));
}
__device__ __forceinline__ void ldsm4(uint32_t& r0, uint32_t& r1, uint32_t& r2, uint32_t& r3,
                                      uint32_t addr) {
    asm volatile("ldmatrix.sync.aligned.m8n8.x4.shared.b16 {%0,%1,%2,%3}, [%4];\n"
                 : "=r"(r0), "=r"(r1), "=r"(r2), "=r"(r3) : "r"(addr));
}
__device__ __forceinline__ void mma_bf16(
    float& d0, float& d1, float& d2, float& d3,
    unsigned a0, unsigned a1, unsigned a2, unsigned a3,
    unsigned b0, unsigned b1)
{
    asm volatile(
        "mma.sync.aligned.m16n8k16.row.col.f32.bf16.bf16.f32 "
        "{%0,%1,%2,%3}, {%4,%5,%6,%7}, {%8,%9}, {%0,%1,%2,%3};\n"
        : "+f"(d0), "+f"(d1), "+f"(d2), "+f"(d3)
        : "r"(a0), "r"(a1), "r"(a2), "r"(a3), "r"(b0), "r"(b1));
}

// ---------------- conversion kernels ----------------
__global__ void k_cvt_hs(const float4* __restrict__ hs4) {
    int i = blockIdx.x * 256 + threadIdx.x;
    if (i < BT*Dq/4) {
        float4 v = hs4[i];
        __nv_bfloat162* o = (__nv_bfloat162*)g_hsb;
        o[2*i]   = __floats2bfloat162_rn(v.x, v.y);
        o[2*i+1] = __floats2bfloat162_rn(v.z, v.w);
    }
}

// Tiled transpose: W[D][V] f32 -> g_wt[VP][D] bf16 (pad rows v>=Vq zeroed)
__global__ void k_cvt_wt(const float* __restrict__ W) {
    __shared__ float tile[32][33];
    int v0 = blockIdx.x * 32, d0 = blockIdx.y * 32;
    int tx = threadIdx.x, ty = threadIdx.y;          // 32 x 8
    #pragma unroll
    for (int i = 0; i < 32; i += 8) {
        int d = d0 + ty + i, v = v0 + tx;
        tile[ty + i][tx] = (v < Vq) ? W[(size_t)d*Vq + v] : 0.0f;
    }
    __syncthreads();
    #pragma unroll
    for (int i = 0; i < 32; i += 8) {
        int v = v0 + ty + i, d = d0 + tx;
        g_wt[(size_t)v*Dq + d] = __float2bfloat16(tile[tx][ty + i]);
    }
}

// ---------------- per-batch symbol maps (parallel first-occurrence) ----------------
__global__ void k_prep(const int* __restrict__ ys_pad) {
    int b = blockIdx.x, tid = threadIdx.x;
    __shared__ int sym[129];
    if (tid == 0) sym[0] = 0;                              // blank
    if (tid >= 1 && tid <= 128) sym[tid] = ys_pad[b*Lq + tid - 1];
    for (int i = tid; i < Vq; i += 256) g_inv[b*Vq + i] = 0x7fffffff;
    __syncthreads();
    if (tid <= 128) atomicMin(&g_inv[b*Vq + sym[tid]], tid);
    __syncthreads();
    if (tid <= 128) g_rep[b*129 + tid] = g_inv[b*Vq + sym[tid]];
    __syncthreads();
    for (int i = tid; i < Vq; i += 256)
        if (g_inv[b*Vq + i] == 0x7fffffff) g_inv[b*Vq + i] = -1;
}

// ---------------- fused bf16 GEMM (cp.async + ldmatrix) + exp-sum + symbol gather ----------------
__global__ __launch_bounds__(256) void k_gemm(const float* __restrict__ bias) {
    const int tid  = threadIdx.x;
    const int lane = tid & 31, wid = tid >> 5;
    const int g  = lane >> 2, tg = lane & 3;
    const int wm = wid & 3,  wn = wid >> 2;         // 4x2 warp grid, warp tile 32x64
    const int n0 = blockIdx.x * 128;
    const int rowg0 = blockIdx.y * 128;
    const int b = rowg0 >> 10;

    __shared__ __align__(16) __nv_bfloat16 As[2][128][40];  // [stage][m][k], KPAD=40 (80B rows, 16B-aligned)
    __shared__ __align__(16) __nv_bfloat16 Bs[2][128][40];  // [stage][n][k]
    __shared__ int   invs[128];
    __shared__ float biass[128];
    __shared__ float rowsum[128][2];

    if (tid < 128) {
        int v = n0 + tid;
        invs[tid]  = (v < Vq) ? g_inv[b*Vq + v] : -1;
        biass[tid] = (v < Vq) ? bias[v] : 0.0f;
    }

    // ldmatrix per-lane byte offsets
    const int lr = lane & 15, lc = (lane >> 4) << 3;        // row-in-tilepair, col 0/8
    const uint32_t aBase = (uint32_t)__cvta_generic_to_shared(&As[0][0][0]);
    const uint32_t bBase = (uint32_t)__cvta_generic_to_shared(&Bs[0][0][0]);
    const uint32_t aoff0 = ((wm*32      + lr)*40 + lc)*2;   // m-subtile 0
    const uint32_t aoff1 = ((wm*32 + 16 + lr)*40 + lc)*2;   // m-subtile 1
    uint32_t boff[4];
    #pragma unroll
    for (int nt = 0; nt < 4; nt++) boff[nt] = ((wn*64 + nt*16 + lr)*40 + lc)*2;

    float acc[2][8][4];
    #pragma unroll
    for (int im = 0; im < 2; im++)
        #pragma unroll
        for (int in_ = 0; in_ < 8; in_++)
            #pragma unroll
            for (int c = 0; c < 4; c++) acc[im][in_][c] = 0.0f;

    // cp.async loader: 4 x 16B per thread per stage (2 A + 2 B)
    const int lrow = tid >> 2, lkp = (tid & 3) << 3;
    auto loadStage = [&](int kt, int st) {
        int k0 = kt * 32;
        #pragma unroll
        for (int j = 0; j < 2; j++) {
            int r = lrow + j*64;
            cp16(&As[st][r][lkp], &g_hsb[(size_t)(rowg0 + r)*Dq + k0 + lkp]);
            cp16(&Bs[st][r][lkp], &g_wt [(size_t)(n0   + r)*Dq + k0 + lkp]);
        }
        asm volatile("cp.async.commit_group;\n");
    };

    loadStage(0, 0);
    for (int kt = 0; kt < 16; kt++) {
        int st = kt & 1;
        if (kt < 15) {
            loadStage(kt + 1, st ^ 1);
            asm volatile("cp.async.wait_group 1;\n");
        } else {
            asm volatile("cp.async.wait_group 0;\n");
        }
        __syncthreads();

        uint32_t ab = aBase + st*10240;
        uint32_t bb = bBase + st*10240;
        #pragma unroll
        for (int ks = 0; ks < 2; ks++) {
            uint32_t ko = ks * 32;                          // 16 elems * 2B
            uint32_t a0[4], a1[4], bm[4][4];
            ldsm4(a0[0], a0[1], a0[2], a0[3], ab + aoff0 + ko);
            ldsm4(a1[0], a1[1], a1[2], a1[3], ab + aoff1 + ko);
            #pragma unroll
            for (int nt = 0; nt < 4; nt++)
                ldsm4(bm[nt][0], bm[nt][1], bm[nt][2], bm[nt][3], bb + boff[nt] + ko);
            #pragma unroll
            for (int nt = 0; nt < 4; nt++) {
                #pragma unroll
                for (int h = 0; h < 2; h++) {
                    int in_ = nt*2 + h;
                    unsigned b0 = bm[nt][h], b1 = bm[nt][2 + h];
                    mma_bf16(acc[0][in_][0], acc[0][in_][1], acc[0][in_][2], acc[0][in_][3],
                             a0[0], a0[1], a0[2], a0[3], b0, b1);
                    mma_bf16(acc[1][in_][0], acc[1][in_][1], acc[1][in_][2], acc[1][in_][3],
                             a1[0], a1[1], a1[2], a1[3], b0, b1);
                }
            }
        }
        __syncthreads();
    }

    // Epilogue: bias add, exp-sum per row, sparse symbol scatter
    #pragma unroll
    for (int im = 0; im < 2; im++) {
        #pragma unroll
        for (int rh = 0; rh < 2; rh++) {
            int m = wm*32 + im*16 + g + rh*8;
            float s = 0.0f;
            #pragma unroll
            for (int in_ = 0; in_ < 8; in_++) {
                #pragma unroll
                for (int cc = 0; cc < 2; cc++) {
                    int n = wn*64 + in_*8 + tg*2 + cc;
                    float x = acc[im][in_][rh*2 + cc] + biass[n];
                    if (n0 + n < Vq) {
                        s += __expf(x);
                        int j = invs[n];
                        if (j >= 0) g_gbuf[(size_t)(rowg0 + m)*130 + j] = x;
                    }
                }
            }
            s += __shfl_xor_sync(0xffffffffu, s, 1);
            s += __shfl_xor_sync(0xffffffffu, s, 2);
            if (tg == 0) rowsum[m][wn] = s;
        }
    }
    __syncthreads();
    if (tid < 128)
        g_partial[(size_t)(rowg0 + tid)*NT + blockIdx.x] = rowsum[tid][0] + rowsum[tid][1];
}

// ---------------- fused: reduce exp-sums -> lse, replicate dups, subtract ----------------
__global__ __launch_bounds__(192) void k_lsedup() {
    int r = blockIdx.x;                  // one row per block
    int t = threadIdx.x;
    __shared__ float ws[6];
    __shared__ float lse_s;
    float s = (t < NT) ? g_partial[(size_t)r*NT + t] : 0.0f;
    #pragma unroll
    for (int o = 16; o > 0; o >>= 1) s += __shfl_xor_sync(0xffffffffu, s, o);
    if ((t & 31) == 0) ws[t >> 5] = s;
    __syncthreads();
    if (t == 0) lse_s = __logf(ws[0] + ws[1] + ws[2] + ws[3] + ws[4] + ws[5]);
    __syncthreads();
    if (t < 129) {
        int bb = r >> 10;
        g_lp[(size_t)r*130 + t] = g_gbuf[(size_t)r*130 + g_rep[bb*129 + t]] - lse_s;
    }
}

// ---------------- CTC forward (unchanged; known correct) ----------------
__global__ __launch_bounds__(288) void k_ctc(const int* __restrict__ ys_pad,
                                             const int* __restrict__ hlens,
                                             const int* __restrict__ ys_lens) {
    const int b = blockIdx.x, s = threadIdx.x;
    __shared__ float bufA[259], bufB[259];
    __shared__ int ysS[128];

    const int hl = hlens[b];
    const int yl = ys_lens[b];
    const float* lpb = g_lp + (size_t)b * Tq * 130;

    if (s < 128) ysS[s] = ys_pad[b*Lq + s];
    if (s < 259) { bufA[s] = NEGF; bufB[s] = NEGF; }
    __syncthreads();

    const bool active = (s < 257);
    int jj = 0;
    bool allow = false;
    if (active && (s & 1)) {
        int k = s >> 1;
        jj = k + 1;
        allow = (k == 0) || (ysS[k] != ysS[k - 1]);
    }

    if (s == 0) bufA[2] = lpb[0];
    if (s == 1) bufA[3] = lpb[1];
    __syncthreads();

    float* cur = bufA;
    float* nxt = bufB;

    float p0 = 0.0f, p1 = 0.0f;
    if (active) {
        p0 = __ldg(&lpb[(size_t)1 * 130 + jj]);
        p1 = __ldg(&lpb[(size_t)2 * 130 + jj]);
    }

    for (int t = 1; t < hl; t++) {
        float lpv = p0;
        p0 = p1;
        int tn = t + 2; if (tn > Tq - 1) tn = Tq - 1;
        if (active) p1 = __ldg(&lpb[(size_t)tn * 130 + jj]);

        if (active) {
            float a1 = cur[2 + s];
            float a2 = cur[1 + s];
            float a3 = allow ? cur[s] : NEGF;
            float m = fmaxf(fmaxf(a1, a2), a3);
            m = fmaxf(m, NEGF);
            float r = __expf(a1 - m) + __expf(a2 - m) + __expf(a3 - m);
            nxt[2 + s] = m + __logf(r) + lpv;
        }
        __syncthreads();
        float* tmp = cur; cur = nxt; nxt = tmp;
    }

    if (s == 0) {
        int i1 = 2 * yl;
        int i2 = i1 - 1; if (i2 < 0) i2 = 0;
        float a = cur[2 + i1], c = cur[2 + i2];
        float m = fmaxf(a, c);
        float ll = m + __logf(__expf(a - m) + __expf(c - m));
        float L = -ll;
        if (!isfinite(L) || L >= 1e29f) L = 0.0f;
        g_loss[b] = L;
    }
}

// ---------------- finalize: sum(loss) / sum(ys_lens) ----------------
__global__ void k_finalize(const int* __restrict__ ys_lens, float* __restrict__ out) {
    int t = threadIdx.x;
    float s  = (t < Bq) ? g_loss[t] : 0.0f;
    float yn = (t < Bq) ? (float)ys_lens[t] : 0.0f;
    #pragma unroll
    for (int o = 16; o > 0; o >>= 1) {
        s  += __shfl_xor_sync(0xffffffffu, s,  o);
        yn += __shfl_xor_sync(0xffffffffu, yn, o);
    }
    if (t == 0) out[0] = s / yn;
}

// ---------------- launch ----------------
extern "C" void kernel_launch(void* const* d_in, const int* in_sizes, int n_in,
                              void* d_out, int out_size) {
    (void)in_sizes; (void)n_in; (void)out_size;
    const float* hs      = (const float*)d_in[0];
    const int*   hlens   = (const int*)  d_in[1];
    const int*   ys_pad  = (const int*)  d_in[2];
    const int*   ys_lens = (const int*)  d_in[3];
    const float* W       = (const float*)d_in[4];
    const float* bias    = (const float*)d_in[5];
    float*       out     = (float*)d_out;

    k_cvt_hs<<<(BT*Dq/4 + 255)/256, 256>>>((const float4*)hs);
    k_cvt_wt<<<dim3(VP/32, Dq/32), dim3(32, 8)>>>(W);
    k_prep  <<<Bq, 256>>>(ys_pad);
    k_gemm  <<<dim3(NT, BT/128), 256>>>(bias);
    k_lsedup<<<BT, 192>>>();
    k_ctc   <<<Bq, 288>>>(ys_pad, hlens, ys_lens);
    k_finalize<<<1, 32>>>(ys_lens, out);
}

// round 9
// speedup vs baseline: 1.5392x; 1.0599x over previous
#include <cuda_runtime.h>
#include <cuda_bf16.h>
#include <cstdint>
#include <math.h>

// Problem constants
#define Bq   16
#define Tq   1024
#define Dq   512
#define Vq   5000
#define Lq   128
#define VP   5120            // V padded to multiple of 128
#define NT   40              // VP / 128 column tiles
#define BT   (Bq*Tq)         // 16384 rows
#define NEGF (-1e30f)

// ---------------- scratch (static device globals; no allocation) ----------------
__device__ __align__(16) __nv_bfloat16 g_hsb[BT*Dq];      // hs in bf16
__device__ __align__(16) __nv_bfloat16 g_wt[VP*Dq];       // W transposed: [v][d], bf16, pad rows zero
__device__ float g_gbuf[BT*130];                          // logits at first-occurrence symbols
__device__ float g_lp[BT*130];                            // log-probs at symbol j
__device__ float g_partial[BT*NT];                        // per-(row, ntile) exp-sums
__device__ int   g_inv[Bq*Vq];                            // vocab -> first symbol index j (or -1)
__device__ int   g_rep[Bq*129];                           // j -> first occurrence j'
__device__ float g_loss[Bq];

// ---------------- helpers ----------------
__device__ __forceinline__ void cp16(void* smem, const void* gmem) {
    uint32_t s = (uint32_t)__cvta_generic_to_shared(smem);
    asm volatile("cp.async.cg.shared.global [%0], [%1], 16;\n" :: "r"(s), "l"(gmem));
}
__device__ __forceinline__ void ldsm4(uint32_t& r0, uint32_t& r1, uint32_t& r2, uint32_t& r3,
                                      uint32_t addr) {
    asm volatile("ldmatrix.sync.aligned.m8n8.x4.shared.b16 {%0,%1,%2,%3}, [%4];\n"
                 : "=r"(r0), "=r"(r1), "=r"(r2), "=r"(r3) : "r"(addr));
}
__device__ __forceinline__ void mma_bf16(
    float& d0, float& d1, float& d2, float& d3,
    unsigned a0, unsigned a1, unsigned a2, unsigned a3,
    unsigned b0, unsigned b1)
{
    asm volatile(
        "mma.sync.aligned.m16n8k16.row.col.f32.bf16.bf16.f32 "
        "{%0,%1,%2,%3}, {%4,%5,%6,%7}, {%8,%9}, {%0,%1,%2,%3};\n"
        : "+f"(d0), "+f"(d1), "+f"(d2), "+f"(d3)
        : "r"(a0), "r"(a1), "r"(a2), "r"(a3), "r"(b0), "r"(b1));
}

// ---------------- conversion kernels ----------------
__global__ void k_cvt_hs(const float4* __restrict__ hs4) {
    int i = blockIdx.x * 256 + threadIdx.x;
    if (i < BT*Dq/4) {
        float4 v = hs4[i];
        __nv_bfloat162* o = (__nv_bfloat162*)g_hsb;
        o[2*i]   = __floats2bfloat162_rn(v.x, v.y);
        o[2*i+1] = __floats2bfloat162_rn(v.z, v.w);
    }
}

// Tiled transpose: W[D][V] f32 -> g_wt[VP][D] bf16 (pad rows v>=Vq zeroed)
__global__ void k_cvt_wt(const float* __restrict__ W) {
    __shared__ float tile[32][33];
    int v0 = blockIdx.x * 32, d0 = blockIdx.y * 32;
    int tx = threadIdx.x, ty = threadIdx.y;          // 32 x 8
    #pragma unroll
    for (int i = 0; i < 32; i += 8) {
        int d = d0 + ty + i, v = v0 + tx;
        tile[ty + i][tx] = (v < Vq) ? W[(size_t)d*Vq + v] : 0.0f;
    }
    __syncthreads();
    #pragma unroll
    for (int i = 0; i < 32; i += 8) {
        int v = v0 + ty + i, d = d0 + tx;
        g_wt[(size_t)v*Dq + d] = __float2bfloat16(tile[tx][ty + i]);
    }
}

// ---------------- per-batch symbol maps (parallel first-occurrence) ----------------
__global__ void k_prep(const int* __restrict__ ys_pad) {
    int b = blockIdx.x, tid = threadIdx.x;
    __shared__ int sym[129];
    if (tid == 0) sym[0] = 0;                              // blank
    if (tid >= 1 && tid <= 128) sym[tid] = ys_pad[b*Lq + tid - 1];
    for (int i = tid; i < Vq; i += 256) g_inv[b*Vq + i] = 0x7fffffff;
    __syncthreads();
    if (tid <= 128) atomicMin(&g_inv[b*Vq + sym[tid]], tid);
    __syncthreads();
    if (tid <= 128) g_rep[b*129 + tid] = g_inv[b*Vq + sym[tid]];
    __syncthreads();
    for (int i = tid; i < Vq; i += 256)
        if (g_inv[b*Vq + i] == 0x7fffffff) g_inv[b*Vq + i] = -1;
}

// ---------------- fused bf16 GEMM: 4-stage cp.async + ldmatrix + mma.sync ----------------
// smem layout (dynamic, bytes):
//   A stages: 4 x 128 x 40 bf16 = 4 x 10240             [0,      40960)
//   B stages: 4 x 128 x 40 bf16 = 4 x 10240             [40960,  81920)
//   bias 128 f32                                        [81920,  82432)
//   invs 128 int                                        [82432,  82944)
//   rsum 128x2 f32                                      [82944,  83968)
#define SMA_OFF   0
#define SMB_OFF   40960
#define SMBIAS    81920
#define SMINVS    82432
#define SMRSUM    82944
#define SM_TOTAL  83968
#define STAGE_B   10240

__global__ __launch_bounds__(256, 2) void k_gemm(const float* __restrict__ bias) {
    extern __shared__ __align__(16) char smem[];
    const int tid  = threadIdx.x;
    const int lane = tid & 31, wid = tid >> 5;
    const int g  = lane >> 2, tg = lane & 3;
    const int wm = wid & 3,  wn = wid >> 2;         // 4x2 warp grid, warp tile 32x64
    const int n0 = blockIdx.x * 128;
    const int rowg0 = blockIdx.y * 128;
    const int b = rowg0 >> 10;

    __nv_bfloat16* As = (__nv_bfloat16*)(smem + SMA_OFF);  // [stage][128][40]
    __nv_bfloat16* Bs = (__nv_bfloat16*)(smem + SMB_OFF);
    float* biass = (float*)(smem + SMBIAS);
    int*   invs  = (int*)  (smem + SMINVS);
    float* rsum  = (float*)(smem + SMRSUM);

    if (tid < 128) {
        int v = n0 + tid;
        invs[tid]  = (v < Vq) ? g_inv[b*Vq + v] : -1;
        biass[tid] = (v < Vq) ? bias[v] : 0.0f;
    }

    // ldmatrix per-lane byte offsets (within one stage)
    const int lr = lane & 15, lc = (lane >> 4) << 3;
    const uint32_t aBase = (uint32_t)__cvta_generic_to_shared(As);
    const uint32_t bBase = (uint32_t)__cvta_generic_to_shared(Bs);
    const uint32_t aoff0 = ((wm*32      + lr)*40 + lc)*2;
    const uint32_t aoff1 = ((wm*32 + 16 + lr)*40 + lc)*2;
    uint32_t boff[4];
    #pragma unroll
    for (int nt = 0; nt < 4; nt++) boff[nt] = ((wn*64 + nt*16 + lr)*40 + lc)*2;

    float acc[2][8][4];
    #pragma unroll
    for (int im = 0; im < 2; im++)
        #pragma unroll
        for (int in_ = 0; in_ < 8; in_++)
            #pragma unroll
            for (int c = 0; c < 4; c++) acc[im][in_][c] = 0.0f;

    // loader: 4 x 16B per thread per stage (2 A rows + 2 B rows); empty commit past end
    const int lrow = tid >> 2, lkp = (tid & 3) << 3;
    auto loadStage = [&](int kt) {
        if (kt < 16) {
            int k0 = kt * 32, st = kt & 3;
            #pragma unroll
            for (int j = 0; j < 2; j++) {
                int r = lrow + j*64;
                cp16(&As[st*5120 + r*40 + lkp], &g_hsb[(size_t)(rowg0 + r)*Dq + k0 + lkp]);
                cp16(&Bs[st*5120 + r*40 + lkp], &g_wt [(size_t)(n0   + r)*Dq + k0 + lkp]);
            }
        }
        asm volatile("cp.async.commit_group;\n");
    };

    loadStage(0);
    loadStage(1);
    loadStage(2);

    #pragma unroll 1
    for (int kt = 0; kt < 16; kt++) {
        asm volatile("cp.async.wait_group 2;\n");
        __syncthreads();                      // stage kt ready; stage (kt-1)&3 free
        loadStage(kt + 3);                    // overlap next loads with this stage's MMAs

        const uint32_t ab = aBase + (kt & 3)*STAGE_B;
        const uint32_t bb = bBase + (kt & 3)*STAGE_B;
        #pragma unroll
        for (int ks = 0; ks < 2; ks++) {
            uint32_t ko = ks * 32;
            uint32_t a0[4], a1[4], bm[4][4];
            ldsm4(a0[0], a0[1], a0[2], a0[3], ab + aoff0 + ko);
            ldsm4(a1[0], a1[1], a1[2], a1[3], ab + aoff1 + ko);
            #pragma unroll
            for (int nt = 0; nt < 4; nt++)
                ldsm4(bm[nt][0], bm[nt][1], bm[nt][2], bm[nt][3], bb + boff[nt] + ko);
            #pragma unroll
            for (int nt = 0; nt < 4; nt++) {
                #pragma unroll
                for (int h = 0; h < 2; h++) {
                    int in_ = nt*2 + h;
                    unsigned b0 = bm[nt][h], b1 = bm[nt][2 + h];
                    mma_bf16(acc[0][in_][0], acc[0][in_][1], acc[0][in_][2], acc[0][in_][3],
                             a0[0], a0[1], a0[2], a0[3], b0, b1);
                    mma_bf16(acc[1][in_][0], acc[1][in_][1], acc[1][in_][2], acc[1][in_][3],
                             a1[0], a1[1], a1[2], a1[3], b0, b1);
                }
            }
        }
    }
    __syncthreads();   // all MMAs done before rsum reuse below

    // Epilogue: bias add, exp-sum per row, sparse symbol scatter
    #pragma unroll
    for (int im = 0; im < 2; im++) {
        #pragma unroll
        for (int rh = 0; rh < 2; rh++) {
            int m = wm*32 + im*16 + g + rh*8;
            float s = 0.0f;
            #pragma unroll
            for (int in_ = 0; in_ < 8; in_++) {
                #pragma unroll
                for (int cc = 0; cc < 2; cc++) {
                    int n = wn*64 + in_*8 + tg*2 + cc;
                    float x = acc[im][in_][rh*2 + cc] + biass[n];
                    if (n0 + n < Vq) {
                        s += __expf(x);
                        int j = invs[n];
                        if (j >= 0) g_gbuf[(size_t)(rowg0 + m)*130 + j] = x;
                    }
                }
            }
            s += __shfl_xor_sync(0xffffffffu, s, 1);
            s += __shfl_xor_sync(0xffffffffu, s, 2);
            if (tg == 0) rsum[m*2 + wn] = s;
        }
    }
    __syncthreads();
    if (tid < 128)
        g_partial[(size_t)(rowg0 + tid)*NT + blockIdx.x] = rsum[tid*2] + rsum[tid*2 + 1];
}

// ---------------- fused: reduce exp-sums -> lse, replicate dups, subtract ----------------
__global__ __launch_bounds__(192) void k_lsedup() {
    int r = blockIdx.x;
    int t = threadIdx.x;
    __shared__ float ws[6];
    __shared__ float lse_s;
    float s = (t < NT) ? g_partial[(size_t)r*NT + t] : 0.0f;
    #pragma unroll
    for (int o = 16; o > 0; o >>= 1) s += __shfl_xor_sync(0xffffffffu, s, o);
    if ((t & 31) == 0) ws[t >> 5] = s;
    __syncthreads();
    if (t == 0) lse_s = __logf(ws[0] + ws[1] + ws[2] + ws[3] + ws[4] + ws[5]);
    __syncthreads();
    if (t < 129) {
        int bb = r >> 10;
        g_lp[(size_t)r*130 + t] = g_gbuf[(size_t)r*130 + g_rep[bb*129 + t]] - lse_s;
    }
}

// ---------------- CTC forward (unchanged; known correct) ----------------
__global__ __launch_bounds__(288) void k_ctc(const int* __restrict__ ys_pad,
                                             const int* __restrict__ hlens,
                                             const int* __restrict__ ys_lens) {
    const int b = blockIdx.x, s = threadIdx.x;
    __shared__ float bufA[259], bufB[259];
    __shared__ int ysS[128];

    const int hl = hlens[b];
    const int yl = ys_lens[b];
    const float* lpb = g_lp + (size_t)b * Tq * 130;

    if (s < 128) ysS[s] = ys_pad[b*Lq + s];
    if (s < 259) { bufA[s] = NEGF; bufB[s] = NEGF; }
    __syncthreads();

    const bool active = (s < 257);
    int jj = 0;
    bool allow = false;
    if (active && (s & 1)) {
        int k = s >> 1;
        jj = k + 1;
        allow = (k == 0) || (ysS[k] != ysS[k - 1]);
    }

    if (s == 0) bufA[2] = lpb[0];
    if (s == 1) bufA[3] = lpb[1];
    __syncthreads();

    float* cur = bufA;
    float* nxt = bufB;

    float p0 = 0.0f, p1 = 0.0f;
    if (active) {
        p0 = __ldg(&lpb[(size_t)1 * 130 + jj]);
        p1 = __ldg(&lpb[(size_t)2 * 130 + jj]);
    }

    for (int t = 1; t < hl; t++) {
        float lpv = p0;
        p0 = p1;
        int tn = t + 2; if (tn > Tq - 1) tn = Tq - 1;
        if (active) p1 = __ldg(&lpb[(size_t)tn * 130 + jj]);

        if (active) {
            float a1 = cur[2 + s];
            float a2 = cur[1 + s];
            float a3 = allow ? cur[s] : NEGF;
            float m = fmaxf(fmaxf(a1, a2), a3);
            m = fmaxf(m, NEGF);
            float r = __expf(a1 - m) + __expf(a2 - m) + __expf(a3 - m);
            nxt[2 + s] = m + __logf(r) + lpv;
        }
        __syncthreads();
        float* tmp = cur; cur = nxt; nxt = tmp;
    }

    if (s == 0) {
        int i1 = 2 * yl;
        int i2 = i1 - 1; if (i2 < 0) i2 = 0;
        float a = cur[2 + i1], c = cur[2 + i2];
        float m = fmaxf(a, c);
        float ll = m + __logf(__expf(a - m) + __expf(c - m));
        float L = -ll;
        if (!isfinite(L) || L >= 1e29f) L = 0.0f;
        g_loss[b] = L;
    }
}

// ---------------- finalize: sum(loss) / sum(ys_lens) ----------------
__global__ void k_finalize(const int* __restrict__ ys_lens, float* __restrict__ out) {
    int t = threadIdx.x;
    float s  = (t < Bq) ? g_loss[t] : 0.0f;
    float yn = (t < Bq) ? (float)ys_lens[t] : 0.0f;
    #pragma unroll
    for (int o = 16; o > 0; o >>= 1) {
        s  += __shfl_xor_sync(0xffffffffu, s,  o);
        yn += __shfl_xor_sync(0xffffffffu, yn, o);
    }
    if (t == 0) out[0] = s / yn;
}

// ---------------- launch ----------------
extern "C" void kernel_launch(void* const* d_in, const int* in_sizes, int n_in,
                              void* d_out, int out_size) {
    (void)in_sizes; (void)n_in; (void)out_size;
    const float* hs      = (const float*)d_in[0];
    const int*   hlens   = (const int*)  d_in[1];
    const int*   ys_pad  = (const int*)  d_in[2];
    const int*   ys_lens = (const int*)  d_in[3];
    const float* W       = (const float*)d_in[4];
    const float* bias    = (const float*)d_in[5];
    float*       out     = (float*)d_out;

    cudaFuncSetAttribute(k_gemm, cudaFuncAttributeMaxDynamicSharedMemorySize, SM_TOTAL);

    k_cvt_hs<<<(BT*Dq/4 + 255)/256, 256>>>((const float4*)hs);
    k_cvt_wt<<<dim3(VP/32, Dq/32), dim3(32, 8)>>>(W);
    k_prep  <<<Bq, 256>>>(ys_pad);
    k_gemm  <<<dim3(NT, BT/128), 256, SM_TOTAL>>>(bias);
    k_lsedup<<<BT, 192>>>();
    k_ctc   <<<Bq, 288>>>(ys_pad, hlens, ys_lens);
    k_finalize<<<1, 32>>>(ys_lens, out);
}